// round 1
// baseline (speedup 1.0000x reference)
#include <cuda_runtime.h>

#define N_MAX 100000
#define SLOT 64

// ---------------- scratch (device globals; no allocations) ----------------
__device__ __align__(16) float g_featn[N_MAX * 8];
__device__ __align__(16) float g_h0[N_MAX * 24];
__device__ float g_deg[N_MAX];
__device__ int   g_indeg[N_MAX];
__device__ int   g_csr_src[N_MAX * SLOT];
__device__ float g_csr_w[N_MAX * SLOT];
__device__ __align__(16) float g_agg[N_MAX * 64];
__device__ __align__(16) float g_out0[N_MAX * 64];
__device__ __align__(16) float g_out1[N_MAX * 64];
__device__ __align__(16) float g_m2[N_MAX * 32];

// ---------------- fast activations (err ~2^-22, safe for 1e-3 tol) --------
__device__ __forceinline__ float fsig(float x) {
    return __fdividef(1.0f, 1.0f + __expf(-x));
}
__device__ __forceinline__ float ftanh_(float x) {
    // tanh(x) = 1 - 2/(e^{2x}+1); exp overflow -> inf -> 1, underflow -> -1 (correct limits)
    return 1.0f - __fdividef(2.0f, __expf(2.0f * x) + 1.0f);
}

// ---------------- kernels ----------------
__global__ void k_zero(int n) {
    int i = blockIdx.x * blockDim.x + threadIdx.x;
    if (i < n) { g_deg[i] = 0.0f; g_indeg[i] = 0; }
}

__global__ void k_norm(const float* __restrict__ feat, int n) {
    int i = blockIdx.x * blockDim.x + threadIdx.x;
    if (i >= n) return;
    const float* f = feat + (size_t)i * 8;
    float v[8];
    float s = 0.0f;
#pragma unroll
    for (int k = 0; k < 8; k++) { v[k] = f[k]; s += v[k]; }
    float inv = __fdividef(1.0f, s);
    float* o = g_featn + (size_t)i * 8;
#pragma unroll
    for (int k = 0; k < 8; k++) o[k] = v[k] * inv;
}

__global__ void k_deg(const int* __restrict__ esrc, const float* __restrict__ ew, int E) {
    int e = blockIdx.x * blockDim.x + threadIdx.x;
    if (e < E) atomicAdd(&g_deg[esrc[e]], ew[e]);
}

__global__ void k_fill(const int* __restrict__ edst, int E) {
    int e = blockIdx.x * blockDim.x + threadIdx.x;
    if (e >= E) return;
    int d = edst[e];
    int p = atomicAdd(&g_indeg[d], 1);
    if (p < SLOT) g_csr_src[d * SLOT + p] = e;   // store edge id for now
}

// sort edge ids per dst (determinism), then rewrite as (src, norm_w)
__global__ void k_sortfix(const int* __restrict__ esrc, const float* __restrict__ ew, int n) {
    int i = blockIdx.x * blockDim.x + threadIdx.x;
    if (i >= n) return;
    int cnt = g_indeg[i];
    if (cnt > SLOT) { cnt = SLOT; g_indeg[i] = SLOT; }
    int ids[SLOT];
    for (int p = 0; p < cnt; p++) ids[p] = g_csr_src[i * SLOT + p];
    for (int p = 1; p < cnt; p++) {          // insertion sort ascending (unique ids)
        int key = ids[p];
        int q = p - 1;
        while (q >= 0 && ids[q] > key) { ids[q + 1] = ids[q]; q--; }
        ids[q + 1] = key;
    }
    float di = g_deg[i];
    for (int p = 0; p < cnt; p++) {
        int e = ids[p];
        int s = esrc[e];
        g_csr_src[i * SLOT + p] = s;
        g_csr_w[i * SLOT + p] = ew[e] * rsqrtf(g_deg[s] * di);
    }
}

// one node per thread; weights broadcast from shared
__global__ void __launch_bounds__(128) k_lstm(const float* __restrict__ Wih,
                                              const float* __restrict__ Whh,
                                              const float* __restrict__ bih,
                                              const float* __restrict__ bhh, int n) {
    __shared__ alignas(16) float sWih[64 * 8];
    __shared__ alignas(16) float sWhh[64 * 16];
    __shared__ float sB[64];
    int tid = threadIdx.x;
    for (int j = tid; j < 512; j += 128) sWih[j] = Wih[j];
    for (int j = tid; j < 1024; j += 128) sWhh[j] = Whh[j];
    if (tid < 64) sB[tid] = bih[tid] + bhh[tid];
    __syncthreads();
    int i = blockIdx.x * 128 + tid;
    if (i >= n) return;

    float h[16], c[16];
#pragma unroll
    for (int k = 0; k < 16; k++) { h[k] = 0.0f; c[k] = 0.0f; }

    int vmax = (i < 5) ? i : 5;
    int start = (i >= 5) ? (i - 5) : 0;

    float fx[8];
#pragma unroll
    for (int k = 0; k < 8; k++) fx[k] = g_featn[(size_t)i * 8 + k];

    for (int t = 0; t < 5; t++) {
        float x[8];
        if (t < vmax) {
            const float* xp = g_featn + (size_t)(start + t) * 8;
#pragma unroll
            for (int k = 0; k < 8; k++) x[k] = xp[k];
        } else {
#pragma unroll
            for (int k = 0; k < 8; k++) x[k] = 0.0f;
        }
        float hn[16];
#pragma unroll
        for (int j = 0; j < 16; j++) {
            float gi = sB[j], gf = sB[j + 16], gg = sB[j + 32], go = sB[j + 48];
#pragma unroll
            for (int k = 0; k < 8; k++) {
                gi += x[k] * sWih[j * 8 + k];
                gf += x[k] * sWih[(j + 16) * 8 + k];
                gg += x[k] * sWih[(j + 32) * 8 + k];
                go += x[k] * sWih[(j + 48) * 8 + k];
            }
#pragma unroll
            for (int k = 0; k < 16; k++) {
                gi += h[k] * sWhh[j * 16 + k];
                gf += h[k] * sWhh[(j + 16) * 16 + k];
                gg += h[k] * sWhh[(j + 32) * 16 + k];
                go += h[k] * sWhh[(j + 48) * 16 + k];
            }
            float cj = fsig(gf) * c[j] + fsig(gi) * ftanh_(gg);
            c[j] = cj;
            hn[j] = fsig(go) * ftanh_(cj);
        }
#pragma unroll
        for (int j = 0; j < 16; j++) h[j] = hn[j];
    }

    float* o = g_h0 + (size_t)i * 24;
#pragma unroll
    for (int k = 0; k < 8; k++) o[k] = fx[k];
#pragma unroll
    for (int j = 0; j < 16; j++) o[8 + j] = h[j];
}

// small GEMM: Out[n,OUT] = act(A[n,IN] @ W[IN,OUT] + B)
template <int IN, int OUT, bool ACT>
__global__ void __launch_bounds__(64) k_gemm(const float* __restrict__ A,
                                             const float* __restrict__ W,
                                             const float* __restrict__ B,
                                             float* __restrict__ Out, int n) {
    __shared__ alignas(16) float sW[IN * OUT];
    __shared__ float sB[OUT];
    __shared__ float sA[64 * (IN + 1)];
    int tid = threadIdx.x;
    for (int j = tid; j < IN * OUT; j += 64) sW[j] = W[j];
    if (tid < OUT) sB[tid] = B ? B[tid] : 0.0f;
    int base = blockIdx.x * 64;
    int lim = n - base;
    if (lim > 64) lim = 64;
    for (int idx = tid; idx < lim * IN; idx += 64) {
        int r = idx / IN;
        int cc = idx - r * IN;
        sA[r * (IN + 1) + cc] = A[(size_t)base * IN + idx];
    }
    __syncthreads();
    if (tid >= lim) return;
    float acc[OUT];
#pragma unroll
    for (int j = 0; j < OUT; j++) acc[j] = sB[j];
    const float* a = sA + tid * (IN + 1);
#pragma unroll 4
    for (int k = 0; k < IN; k++) {
        float av = a[k];
#pragma unroll
        for (int j = 0; j < OUT; j += 4) {
            float4 w = *reinterpret_cast<const float4*>(sW + k * OUT + j);
            acc[j] += av * w.x;
            acc[j + 1] += av * w.y;
            acc[j + 2] += av * w.z;
            acc[j + 3] += av * w.w;
        }
    }
    float* o = Out + (size_t)(base + tid) * OUT;
#pragma unroll
    for (int j = 0; j < OUT; j++) {
        float v = acc[j];
        if (ACT) v = (v > 0.0f) ? v : 0.01f * v;
        o[j] = v;
    }
}

// warp-per-dst CSR gather: Dst[i] = sum_e w_e * S[src_e]  (+ bias at FINAL)
template <int D, bool FINAL>
__global__ void k_agg(const float* __restrict__ S, const float* __restrict__ bias,
                      float* __restrict__ Dst, int n) {
    int w = (blockIdx.x * blockDim.x + threadIdx.x) >> 5;
    int lane = threadIdx.x & 31;
    if (w >= n) return;
    int cnt = g_indeg[w];
    const int* cs = g_csr_src + (size_t)w * SLOT;
    const float* cw = g_csr_w + (size_t)w * SLOT;
    float a0 = 0.0f, a1 = 0.0f;
#pragma unroll 4
    for (int e = 0; e < cnt; e++) {
        int s = cs[e];
        float ww = cw[e];
        if (D == 64) {
            a0 += ww * S[(size_t)s * 64 + lane];
            a1 += ww * S[(size_t)s * 64 + 32 + lane];
        } else {
            if (lane < D) a0 += ww * S[(size_t)s * D + lane];
        }
    }
    if (D == 64) {
        Dst[(size_t)w * 64 + lane] = a0;
        Dst[(size_t)w * 64 + 32 + lane] = a1;
    } else if (lane < D) {
        float v = a0;
        if (FINAL) v += bias[lane];
        Dst[(size_t)w * D + lane] = v;
    }
}

// ---------------- launch ----------------
extern "C" void kernel_launch(void* const* d_in, const int* in_sizes, int n_in,
                              void* d_out, int out_size) {
    const float* feat = (const float*)d_in[0];
    const int* esrc = (const int*)d_in[1];
    const int* edst = (const int*)d_in[2];
    const float* ew = (const float*)d_in[3];
    const float* Wih = (const float*)d_in[4];
    const float* Whh = (const float*)d_in[5];
    const float* bih = (const float*)d_in[6];
    const float* bhh = (const float*)d_in[7];
    const float* W0 = (const float*)d_in[8];
    const float* b0 = (const float*)d_in[9];
    const float* W1 = (const float*)d_in[10];
    const float* b1 = (const float*)d_in[11];
    const float* W2 = (const float*)d_in[12];
    const float* b2 = (const float*)d_in[13];
    float* out = (float*)d_out;

    int n = in_sizes[0] / 8;
    int E = in_sizes[1];

    void *p_h0, *p_agg, *p_out0, *p_out1, *p_m2;
    cudaGetSymbolAddress(&p_h0, g_h0);
    cudaGetSymbolAddress(&p_agg, g_agg);
    cudaGetSymbolAddress(&p_out0, g_out0);
    cudaGetSymbolAddress(&p_out1, g_out1);
    cudaGetSymbolAddress(&p_m2, g_m2);

    const int TB = 256;
    k_zero<<<(n + TB - 1) / TB, TB>>>(n);
    k_norm<<<(n + TB - 1) / TB, TB>>>(feat, n);
    k_deg<<<(E + TB - 1) / TB, TB>>>(esrc, ew, E);
    k_fill<<<(E + TB - 1) / TB, TB>>>(edst, E);
    k_sortfix<<<(n + TB - 1) / TB, TB>>>(esrc, ew, n);
    k_lstm<<<(n + 127) / 128, 128>>>(Wih, Whh, bih, bhh, n);

    const int AT = 256;                 // 8 warps/block, warp per node
    int aggBlocks = (n + (AT / 32) - 1) / (AT / 32);

    // layer 0: aggregate h0 (24) first, then GEMM 24->64 + bias + leaky
    k_agg<24, false><<<aggBlocks, AT>>>((const float*)p_h0, nullptr, (float*)p_agg, n);
    k_gemm<24, 64, true><<<(n + 63) / 64, 64>>>((const float*)p_agg, W0, b0, (float*)p_out0, n);

    // layer 1: aggregate out0 (64), then GEMM 64->64 + bias + leaky
    k_agg<64, false><<<aggBlocks, AT>>>((const float*)p_out0, nullptr, (float*)p_agg, n);
    k_gemm<64, 64, true><<<(n + 63) / 64, 64>>>((const float*)p_agg, W1, b1, (float*)p_out1, n);

    // layer 2: GEMM 64->32 (no bias/act), then aggregate (32) + bias -> output
    k_gemm<64, 32, false><<<(n + 63) / 64, 64>>>((const float*)p_out1, W2, nullptr, (float*)p_m2, n);
    k_agg<32, true><<<aggBlocks, AT>>>((const float*)p_m2, b2, out, n);
}

// round 2
// speedup vs baseline: 1.0560x; 1.0560x over previous
#include <cuda_runtime.h>

#define N_MAX 100000
#define SLOT 64

// ---------------- scratch (device globals; no allocations) ----------------
__device__ __align__(16) float g_featn[N_MAX * 8];
__device__ __align__(16) float g_U[N_MAX * 64];      // featn @ W_ih^T + bias
__device__ __align__(16) float g_h0[N_MAX * 32];     // [featn(8) | lstm_h(16) | 0(8)]
__device__ float g_deg[N_MAX];
__device__ int   g_indeg[N_MAX];
__device__ int   g_csr_src[N_MAX * SLOT];
__device__ float g_csr_w[N_MAX * SLOT];
__device__ __align__(16) float g_agg[N_MAX * 64];
__device__ __align__(16) float g_out0[N_MAX * 64];
__device__ __align__(16) float g_out1[N_MAX * 64];
__device__ __align__(16) float g_m2[N_MAX * 32];

// ---------------- fast activations (err ~2^-22, safe for 1e-3 tol) --------
__device__ __forceinline__ float fsig(float x) {
    return __fdividef(1.0f, 1.0f + __expf(-x));
}
__device__ __forceinline__ float ftanh_(float x) {
    return 1.0f - __fdividef(2.0f, __expf(2.0f * x) + 1.0f);
}

// ---------------- kernels ----------------
__global__ void k_zero(int n) {
    int i = blockIdx.x * blockDim.x + threadIdx.x;
    if (i < n) { g_deg[i] = 0.0f; g_indeg[i] = 0; }
}

// row-normalize feat AND compute U = featn @ W_ih^T + (b_ih + b_hh)
__global__ void __launch_bounds__(256) k_norm_u(const float* __restrict__ feat,
                                                const float* __restrict__ Wih,
                                                const float* __restrict__ bih,
                                                const float* __restrict__ bhh, int n) {
    __shared__ float sWih[64 * 8];
    __shared__ float sB[64];
    int tid = threadIdx.x;
    for (int j = tid; j < 512; j += 256) sWih[j] = Wih[j];
    if (tid < 64) sB[tid] = bih[tid] + bhh[tid];
    __syncthreads();
    int i = blockIdx.x * 256 + tid;
    if (i >= n) return;

    const float4* f4 = reinterpret_cast<const float4*>(feat + (size_t)i * 8);
    float4 a = f4[0], b = f4[1];
    float v[8] = {a.x, a.y, a.z, a.w, b.x, b.y, b.z, b.w};
    float s = 0.0f;
#pragma unroll
    for (int k = 0; k < 8; k++) s += v[k];
    float inv = __fdividef(1.0f, s);
#pragma unroll
    for (int k = 0; k < 8; k++) v[k] *= inv;
    float4* o4 = reinterpret_cast<float4*>(g_featn + (size_t)i * 8);
    o4[0] = make_float4(v[0], v[1], v[2], v[3]);
    o4[1] = make_float4(v[4], v[5], v[6], v[7]);

    float4* u4 = reinterpret_cast<float4*>(g_U + (size_t)i * 64);
#pragma unroll
    for (int j4 = 0; j4 < 16; j4++) {
        float uu[4];
#pragma unroll
        for (int jj = 0; jj < 4; jj++) {
            int j = j4 * 4 + jj;
            float u = sB[j];
#pragma unroll
            for (int k = 0; k < 8; k++) u += v[k] * sWih[j * 8 + k];
            uu[jj] = u;
        }
        u4[j4] = make_float4(uu[0], uu[1], uu[2], uu[3]);
    }
}

// fused degree + CSR slot fill (stores edge id)
__global__ void k_edge(const int* __restrict__ esrc, const int* __restrict__ edst,
                       const float* __restrict__ ew, int E) {
    int e = blockIdx.x * blockDim.x + threadIdx.x;
    if (e >= E) return;
    atomicAdd(&g_deg[esrc[e]], ew[e]);
    int d = edst[e];
    int p = atomicAdd(&g_indeg[d], 1);
    if (p < SLOT) g_csr_src[d * SLOT + p] = e;
}

// sort edge ids per dst (replay determinism), rewrite as (src, norm_w)
__global__ void k_sortfix(const int* __restrict__ esrc, const float* __restrict__ ew, int n) {
    int i = blockIdx.x * blockDim.x + threadIdx.x;
    if (i >= n) return;
    int cnt = g_indeg[i];
    if (cnt > SLOT) { cnt = SLOT; g_indeg[i] = SLOT; }
    int ids[SLOT];
    for (int p = 0; p < cnt; p++) ids[p] = g_csr_src[i * SLOT + p];
    for (int p = 1; p < cnt; p++) {
        int key = ids[p];
        int q = p - 1;
        while (q >= 0 && ids[q] > key) { ids[q + 1] = ids[q]; q--; }
        ids[q + 1] = key;
    }
    float di = g_deg[i];
    for (int p = 0; p < cnt; p++) {
        int e = ids[p];
        int s = esrc[e];
        g_csr_src[i * SLOT + p] = s;
        g_csr_w[i * SLOT + p] = ew[e] * rsqrtf(g_deg[s] * di);
    }
}

// LSTM over 5-step window; input projection already in g_U
__global__ void __launch_bounds__(128) k_lstm(int n) {
    __shared__ float sWhh[64 * 16];
    __shared__ float sB[64];
    int tid = threadIdx.x;
    extern __shared__ float dummy[];
    // (static shared only)
    {
        // weights loaded from g_U producer's companions: passed via const mem? Use params.
    }
    // NOTE: weights come through kernel params (see launch)
    // placeholder removed below
    int i = blockIdx.x * 128 + tid;
    (void)i; (void)dummy;
}

// real LSTM kernel (above stub unused; kept minimal): define properly
__global__ void __launch_bounds__(128) k_lstm2(const float* __restrict__ Whh,
                                               const float* __restrict__ bih,
                                               const float* __restrict__ bhh, int n) {
    __shared__ float sWhh[64 * 16];
    __shared__ float sB[64];
    int tid = threadIdx.x;
    for (int j = tid; j < 1024; j += 128) sWhh[j] = Whh[j];
    if (tid < 64) sB[tid] = bih[tid] + bhh[tid];
    __syncthreads();
    int i = blockIdx.x * 128 + tid;
    if (i >= n) return;

    float h[16], c[16];
#pragma unroll
    for (int k = 0; k < 16; k++) { h[k] = 0.0f; c[k] = 0.0f; }

    int vmax = (i < 5) ? i : 5;
    int base = (i >= 5) ? (i - 5) : 0;

    for (int t = 0; t < 5; t++) {
        float g[64];
        if (t < vmax) {
            const float4* up = reinterpret_cast<const float4*>(g_U + (size_t)(base + t) * 64);
#pragma unroll
            for (int q = 0; q < 16; q++) {
                float4 u = up[q];
                g[q * 4] = u.x; g[q * 4 + 1] = u.y; g[q * 4 + 2] = u.z; g[q * 4 + 3] = u.w;
            }
        } else {
#pragma unroll
            for (int j = 0; j < 64; j++) g[j] = sB[j];
        }
        float hn[16];
#pragma unroll
        for (int j = 0; j < 16; j++) {
            float gi = g[j], gf = g[j + 16], gg = g[j + 32], go = g[j + 48];
#pragma unroll
            for (int k = 0; k < 16; k++) {
                gi += h[k] * sWhh[j * 16 + k];
                gf += h[k] * sWhh[(j + 16) * 16 + k];
                gg += h[k] * sWhh[(j + 32) * 16 + k];
                go += h[k] * sWhh[(j + 48) * 16 + k];
            }
            float cj = fsig(gf) * c[j] + fsig(gi) * ftanh_(gg);
            c[j] = cj;
            hn[j] = fsig(go) * ftanh_(cj);
        }
#pragma unroll
        for (int j = 0; j < 16; j++) h[j] = hn[j];
    }

    // h0 row (stride 32): featn(8) | h(16) | zeros(8)
    float4* o4 = reinterpret_cast<float4*>(g_h0 + (size_t)i * 32);
    const float4* f4 = reinterpret_cast<const float4*>(g_featn + (size_t)i * 8);
    o4[0] = f4[0];
    o4[1] = f4[1];
    o4[2] = make_float4(h[0], h[1], h[2], h[3]);
    o4[3] = make_float4(h[4], h[5], h[6], h[7]);
    o4[4] = make_float4(h[8], h[9], h[10], h[11]);
    o4[5] = make_float4(h[12], h[13], h[14], h[15]);
    o4[6] = make_float4(0.f, 0.f, 0.f, 0.f);
    o4[7] = make_float4(0.f, 0.f, 0.f, 0.f);
}

// GEMM: Out[n,OUT] (stride OUT) = act(A[n, :IN] (stride AS) @ W[IN,OUT] + B)
template <int IN, int OUT, int AS, bool ACT>
__global__ void __launch_bounds__(128) k_gemm(const float* __restrict__ A,
                                              const float* __restrict__ W,
                                              const float* __restrict__ B,
                                              float* __restrict__ Out, int n) {
    __shared__ float4 sW[IN * OUT / 4];
    __shared__ float sB[OUT];
    int tid = threadIdx.x;
    const float4* W4 = reinterpret_cast<const float4*>(W);
    for (int j = tid; j < IN * OUT / 4; j += 128) sW[j] = W4[j];
    if (tid < OUT) sB[tid] = B ? B[tid] : 0.0f;
    __syncthreads();
    int i = blockIdx.x * 128 + tid;
    if (i >= n) return;

    float acc[OUT];
#pragma unroll
    for (int j = 0; j < OUT; j++) acc[j] = sB[j];

    const float4* a4 = reinterpret_cast<const float4*>(A + (size_t)i * AS);
#pragma unroll
    for (int k4 = 0; k4 < IN / 4; k4++) {
        float4 a = a4[k4];
        float av[4] = {a.x, a.y, a.z, a.w};
#pragma unroll
        for (int kk = 0; kk < 4; kk++) {
            int k = k4 * 4 + kk;
#pragma unroll
            for (int j4 = 0; j4 < OUT / 4; j4++) {
                float4 w = sW[k * (OUT / 4) + j4];
                acc[j4 * 4] += av[kk] * w.x;
                acc[j4 * 4 + 1] += av[kk] * w.y;
                acc[j4 * 4 + 2] += av[kk] * w.z;
                acc[j4 * 4 + 3] += av[kk] * w.w;
            }
        }
    }
    float4* o4 = reinterpret_cast<float4*>(Out + (size_t)i * OUT);
#pragma unroll
    for (int j4 = 0; j4 < OUT / 4; j4++) {
        float v0 = acc[j4 * 4], v1 = acc[j4 * 4 + 1], v2 = acc[j4 * 4 + 2], v3 = acc[j4 * 4 + 3];
        if (ACT) {
            v0 = (v0 > 0.f) ? v0 : 0.01f * v0;
            v1 = (v1 > 0.f) ? v1 : 0.01f * v1;
            v2 = (v2 > 0.f) ? v2 : 0.01f * v2;
            v3 = (v3 > 0.f) ? v3 : 0.01f * v3;
        }
        o4[j4] = make_float4(v0, v1, v2, v3);
    }
}

// warp-per-dst gather, D=64 floats (16 float4), 2 edges per iteration
__global__ void k_agg64(const float* __restrict__ S, float* __restrict__ Dst, int n) {
    int w = (blockIdx.x * blockDim.x + threadIdx.x) >> 5;
    int lane = threadIdx.x & 31;
    if (w >= n) return;
    int cnt = g_indeg[w];
    const int* cs = g_csr_src + (size_t)w * SLOT;
    const float* cw = g_csr_w + (size_t)w * SLOT;
    int hh = lane >> 4, l = lane & 15;
    const float4* S4 = reinterpret_cast<const float4*>(S);
    float4 acc = make_float4(0.f, 0.f, 0.f, 0.f);
#pragma unroll 4
    for (int e = 0; e < cnt; e += 2) {
        int ee = e + hh;
        bool ok = ee < cnt;
        int s = ok ? cs[ee] : 0;
        float wgt = ok ? cw[ee] : 0.0f;
        float4 v = S4[(size_t)s * 16 + l];
        acc.x += wgt * v.x; acc.y += wgt * v.y; acc.z += wgt * v.z; acc.w += wgt * v.w;
    }
    acc.x += __shfl_xor_sync(0xffffffff, acc.x, 16);
    acc.y += __shfl_xor_sync(0xffffffff, acc.y, 16);
    acc.z += __shfl_xor_sync(0xffffffff, acc.z, 16);
    acc.w += __shfl_xor_sync(0xffffffff, acc.w, 16);
    if (lane < 16) reinterpret_cast<float4*>(Dst)[(size_t)w * 16 + lane] = acc;
}

// warp-per-dst gather, D=32 floats (8 float4), 4 edges per iteration
template <bool FINAL>
__global__ void k_agg32(const float* __restrict__ S, const float* __restrict__ bias,
                        float* __restrict__ Dst, int n) {
    int w = (blockIdx.x * blockDim.x + threadIdx.x) >> 5;
    int lane = threadIdx.x & 31;
    if (w >= n) return;
    int cnt = g_indeg[w];
    const int* cs = g_csr_src + (size_t)w * SLOT;
    const float* cw = g_csr_w + (size_t)w * SLOT;
    int q = lane >> 3, l = lane & 7;
    const float4* S4 = reinterpret_cast<const float4*>(S);
    float4 acc = make_float4(0.f, 0.f, 0.f, 0.f);
#pragma unroll 4
    for (int e = 0; e < cnt; e += 4) {
        int ee = e + q;
        bool ok = ee < cnt;
        int s = ok ? cs[ee] : 0;
        float wgt = ok ? cw[ee] : 0.0f;
        float4 v = S4[(size_t)s * 8 + l];
        acc.x += wgt * v.x; acc.y += wgt * v.y; acc.z += wgt * v.z; acc.w += wgt * v.w;
    }
#pragma unroll
    for (int m = 8; m <= 16; m <<= 1) {
        acc.x += __shfl_xor_sync(0xffffffff, acc.x, m);
        acc.y += __shfl_xor_sync(0xffffffff, acc.y, m);
        acc.z += __shfl_xor_sync(0xffffffff, acc.z, m);
        acc.w += __shfl_xor_sync(0xffffffff, acc.w, m);
    }
    if (lane < 8) {
        if (FINAL) {
            float4 b = reinterpret_cast<const float4*>(bias)[lane];
            acc.x += b.x; acc.y += b.y; acc.z += b.z; acc.w += b.w;
        }
        reinterpret_cast<float4*>(Dst)[(size_t)w * 8 + lane] = acc;
    }
}

// ---------------- launch ----------------
extern "C" void kernel_launch(void* const* d_in, const int* in_sizes, int n_in,
                              void* d_out, int out_size) {
    const float* feat = (const float*)d_in[0];
    const int* esrc = (const int*)d_in[1];
    const int* edst = (const int*)d_in[2];
    const float* ew = (const float*)d_in[3];
    const float* Wih = (const float*)d_in[4];
    const float* Whh = (const float*)d_in[5];
    const float* bih = (const float*)d_in[6];
    const float* bhh = (const float*)d_in[7];
    const float* W0 = (const float*)d_in[8];
    const float* b0 = (const float*)d_in[9];
    const float* W1 = (const float*)d_in[10];
    const float* b1 = (const float*)d_in[11];
    const float* W2 = (const float*)d_in[12];
    const float* b2 = (const float*)d_in[13];
    float* out = (float*)d_out;

    int n = in_sizes[0] / 8;
    int E = in_sizes[1];

    void *p_h0, *p_agg, *p_out0, *p_out1, *p_m2;
    cudaGetSymbolAddress(&p_h0, g_h0);
    cudaGetSymbolAddress(&p_agg, g_agg);
    cudaGetSymbolAddress(&p_out0, g_out0);
    cudaGetSymbolAddress(&p_out1, g_out1);
    cudaGetSymbolAddress(&p_m2, g_m2);

    const int TB = 256;
    k_zero<<<(n + TB - 1) / TB, TB>>>(n);
    k_norm_u<<<(n + 255) / 256, 256>>>(feat, Wih, bih, bhh, n);
    k_edge<<<(E + TB - 1) / TB, TB>>>(esrc, edst, ew, E);
    k_sortfix<<<(n + TB - 1) / TB, TB>>>(esrc, ew, n);
    k_lstm2<<<(n + 127) / 128, 128>>>(Whh, bih, bhh, n);

    const int AT = 256;
    int aggBlocks = (n + (AT / 32) - 1) / (AT / 32);

    // layer 0: aggregate h0 (stride 32, first 24 cols live), then GEMM 24->64
    k_agg32<false><<<aggBlocks, AT>>>((const float*)p_h0, nullptr, (float*)p_agg, n);
    k_gemm<24, 64, 32, true><<<(n + 127) / 128, 128>>>((const float*)p_agg, W0, b0, (float*)p_out0, n);

    // layer 1: aggregate out0 (64), then GEMM 64->64
    k_agg64<<<aggBlocks, AT>>>((const float*)p_out0, (float*)p_agg, n);
    k_gemm<64, 64, 64, true><<<(n + 127) / 128, 128>>>((const float*)p_agg, W1, b1, (float*)p_out1, n);

    // layer 2: GEMM 64->32, then aggregate (32) + bias -> output
    k_gemm<64, 32, 64, false><<<(n + 127) / 128, 128>>>((const float*)p_out1, W2, nullptr, (float*)p_m2, n);
    k_agg32<true><<<aggBlocks, AT>>>((const float*)p_m2, b2, out, n);
}

// round 3
// speedup vs baseline: 1.5854x; 1.5014x over previous
#include <cuda_runtime.h>

#define N_MAX 100000
#define SLOT 64

// ---------------- scratch (device globals; no allocations) ----------------
__device__ __align__(16) float g_featn[N_MAX * 8];
__device__ __align__(16) float g_U[N_MAX * 64];      // gate-interleaved: [i][j(16)][gate(4)]
__device__ __align__(16) float g_h0[N_MAX * 32];     // [featn(8) | lstm_h(16) | 0(8)]
__device__ float g_deg[N_MAX];
__device__ int   g_indeg[N_MAX];
__device__ int   g_csr_src[N_MAX * SLOT];
__device__ float g_csr_w[N_MAX * SLOT];
__device__ __align__(16) float g_agg[N_MAX * 64];
__device__ __align__(16) float g_out0[N_MAX * 64];
__device__ __align__(16) float g_out1[N_MAX * 64];
__device__ __align__(16) float g_m2[N_MAX * 32];

// ---------------- fast activations (err ~2^-22, safe for 1e-3 tol) --------
__device__ __forceinline__ float fsig(float x) {
    return __fdividef(1.0f, 1.0f + __expf(-x));
}
__device__ __forceinline__ float ftanh_(float x) {
    return 1.0f - __fdividef(2.0f, __expf(2.0f * x) + 1.0f);
}

// ---------------- kernels ----------------
__global__ void k_zero(int n) {
    int i = blockIdx.x * blockDim.x + threadIdx.x;
    if (i < n) { g_deg[i] = 0.0f; g_indeg[i] = 0; }
}

// row-normalize feat AND compute gate-interleaved U = featn @ W_ih^T + (b_ih+b_hh)
__global__ void __launch_bounds__(256) k_norm_u(const float* __restrict__ feat,
                                                const float* __restrict__ Wih,
                                                const float* __restrict__ bih,
                                                const float* __restrict__ bhh, int n) {
    __shared__ __align__(16) float sWI[512];  // [j(16)][k(8)][gate(4)]
    __shared__ __align__(16) float sB[64];    // [j(16)][gate(4)]
    int tid = threadIdx.x;
    for (int idx = tid; idx < 512; idx += 256) {
        int g = idx & 3, k = (idx >> 2) & 7, j = idx >> 5;
        sWI[idx] = Wih[(j + 16 * g) * 8 + k];
    }
    if (tid < 64) {
        int g = tid & 3, j = tid >> 2;
        sB[tid] = bih[j + 16 * g] + bhh[j + 16 * g];
    }
    __syncthreads();
    int i = blockIdx.x * 256 + tid;
    if (i >= n) return;

    const float4* f4 = reinterpret_cast<const float4*>(feat + (size_t)i * 8);
    float4 a = f4[0], b = f4[1];
    float v[8] = {a.x, a.y, a.z, a.w, b.x, b.y, b.z, b.w};
    float s = 0.0f;
#pragma unroll
    for (int k = 0; k < 8; k++) s += v[k];
    float inv = __fdividef(1.0f, s);
#pragma unroll
    for (int k = 0; k < 8; k++) v[k] *= inv;
    float4* o4 = reinterpret_cast<float4*>(g_featn + (size_t)i * 8);
    o4[0] = make_float4(v[0], v[1], v[2], v[3]);
    o4[1] = make_float4(v[4], v[5], v[6], v[7]);

    const float4* W4 = reinterpret_cast<const float4*>(sWI);
    const float4* B4 = reinterpret_cast<const float4*>(sB);
    float4* u4 = reinterpret_cast<float4*>(g_U + (size_t)i * 64);
#pragma unroll
    for (int j = 0; j < 16; j++) {
        float4 acc = B4[j];
#pragma unroll
        for (int k = 0; k < 8; k++) {
            float4 w = W4[j * 8 + k];
            acc.x += v[k] * w.x; acc.y += v[k] * w.y;
            acc.z += v[k] * w.z; acc.w += v[k] * w.w;
        }
        u4[j] = acc;
    }
}

// fused degree + CSR slot fill (stores src and raw ew)
__global__ void k_edge(const int* __restrict__ esrc, const int* __restrict__ edst,
                       const float* __restrict__ ew, int E) {
    int e = blockIdx.x * blockDim.x + threadIdx.x;
    if (e >= E) return;
    int s = esrc[e];
    float w = ew[e];
    atomicAdd(&g_deg[s], w);
    int d = edst[e];
    int p = atomicAdd(&g_indeg[d], 1);
    if (p < SLOT) {
        g_csr_src[d * SLOT + p] = s;
        g_csr_w[d * SLOT + p] = w;
    }
}

// warp per node: apply symmetric normalization in place; clamp indeg
__global__ void k_fixw(int n) {
    int i = (blockIdx.x * blockDim.x + threadIdx.x) >> 5;
    int lane = threadIdx.x & 31;
    if (i >= n) return;
    int cnt = g_indeg[i];
    if (cnt > SLOT) { cnt = SLOT; if (lane == 0) g_indeg[i] = SLOT; }
    float di = g_deg[i];
#pragma unroll
    for (int p = lane; p < SLOT; p += 32) {
        if (p < cnt) {
            int s = g_csr_src[(size_t)i * SLOT + p];
            g_csr_w[(size_t)i * SLOT + p] *= rsqrtf(g_deg[s] * di);
        }
    }
}

// LSTM over 5-step window; gate-interleaved U, W_hh in smem gate-interleaved
__global__ void __launch_bounds__(128) k_lstm(const float* __restrict__ Whh,
                                              const float* __restrict__ bih,
                                              const float* __restrict__ bhh, int n) {
    __shared__ __align__(16) float sWhh[1024];  // [(j*16+k)][gate(4)]
    __shared__ __align__(16) float sB[64];      // [j][gate]
    int tid = threadIdx.x;
    for (int idx = tid; idx < 1024; idx += 128) {
        int g = idx & 3, k = (idx >> 2) & 15, j = idx >> 6;
        sWhh[idx] = Whh[(j + 16 * g) * 16 + k];
    }
    if (tid < 64) {
        int g = tid & 3, j = tid >> 2;
        sB[tid] = bih[j + 16 * g] + bhh[j + 16 * g];
    }
    __syncthreads();
    int i = blockIdx.x * 128 + tid;
    if (i >= n) return;

    const float4* W4 = reinterpret_cast<const float4*>(sWhh);
    const float4* B4 = reinterpret_cast<const float4*>(sB);

    float h[16], c[16];
#pragma unroll
    for (int k = 0; k < 16; k++) { h[k] = 0.0f; c[k] = 0.0f; }

    int vmax = (i < 5) ? i : 5;
    int base = (i >= 5) ? (i - 5) : 0;

    for (int t = 0; t < 5; t++) {
        bool valid = (t < vmax);
        const float4* up = reinterpret_cast<const float4*>(g_U + (size_t)(base + t) * 64);
        float hn[16];
#pragma unroll
        for (int j = 0; j < 16; j++) {
            float4 u = valid ? up[j] : B4[j];
            float gi = u.x, gf = u.y, gg = u.z, go = u.w;
#pragma unroll
            for (int k = 0; k < 16; k++) {
                float4 w = W4[j * 16 + k];
                float hk = h[k];
                gi += hk * w.x; gf += hk * w.y; gg += hk * w.z; go += hk * w.w;
            }
            float cj = fsig(gf) * c[j] + fsig(gi) * ftanh_(gg);
            c[j] = cj;
            hn[j] = fsig(go) * ftanh_(cj);
        }
#pragma unroll
        for (int j = 0; j < 16; j++) h[j] = hn[j];
    }

    float4* o4 = reinterpret_cast<float4*>(g_h0 + (size_t)i * 32);
    const float4* f4 = reinterpret_cast<const float4*>(g_featn + (size_t)i * 8);
    o4[0] = f4[0];
    o4[1] = f4[1];
    o4[2] = make_float4(h[0], h[1], h[2], h[3]);
    o4[3] = make_float4(h[4], h[5], h[6], h[7]);
    o4[4] = make_float4(h[8], h[9], h[10], h[11]);
    o4[5] = make_float4(h[12], h[13], h[14], h[15]);
    o4[6] = make_float4(0.f, 0.f, 0.f, 0.f);
    o4[7] = make_float4(0.f, 0.f, 0.f, 0.f);
}

// GEMM: Out[n,OUT] (stride OUT) = act(A[n, :IN] (stride AS) @ W[IN,OUT] + B)
template <int IN, int OUT, int AS, bool ACT>
__global__ void __launch_bounds__(128) k_gemm(const float* __restrict__ A,
                                              const float* __restrict__ W,
                                              const float* __restrict__ B,
                                              float* __restrict__ Out, int n) {
    __shared__ float4 sW[IN * OUT / 4];
    __shared__ float sB[OUT];
    int tid = threadIdx.x;
    const float4* W4 = reinterpret_cast<const float4*>(W);
    for (int j = tid; j < IN * OUT / 4; j += 128) sW[j] = W4[j];
    if (tid < OUT) sB[tid] = B ? B[tid] : 0.0f;
    __syncthreads();
    int i = blockIdx.x * 128 + tid;
    if (i >= n) return;

    float acc[OUT];
#pragma unroll
    for (int j = 0; j < OUT; j++) acc[j] = sB[j];

    const float4* a4 = reinterpret_cast<const float4*>(A + (size_t)i * AS);
#pragma unroll
    for (int k4 = 0; k4 < IN / 4; k4++) {
        float4 a = a4[k4];
        float av[4] = {a.x, a.y, a.z, a.w};
#pragma unroll
        for (int kk = 0; kk < 4; kk++) {
            int k = k4 * 4 + kk;
#pragma unroll
            for (int j4 = 0; j4 < OUT / 4; j4++) {
                float4 w = sW[k * (OUT / 4) + j4];
                acc[j4 * 4] += av[kk] * w.x;
                acc[j4 * 4 + 1] += av[kk] * w.y;
                acc[j4 * 4 + 2] += av[kk] * w.z;
                acc[j4 * 4 + 3] += av[kk] * w.w;
            }
        }
    }
    float4* o4 = reinterpret_cast<float4*>(Out + (size_t)i * OUT);
#pragma unroll
    for (int j4 = 0; j4 < OUT / 4; j4++) {
        float v0 = acc[j4 * 4], v1 = acc[j4 * 4 + 1], v2 = acc[j4 * 4 + 2], v3 = acc[j4 * 4 + 3];
        if (ACT) {
            v0 = (v0 > 0.f) ? v0 : 0.01f * v0;
            v1 = (v1 > 0.f) ? v1 : 0.01f * v1;
            v2 = (v2 > 0.f) ? v2 : 0.01f * v2;
            v3 = (v3 > 0.f) ? v3 : 0.01f * v3;
        }
        o4[j4] = make_float4(v0, v1, v2, v3);
    }
}

// warp-per-dst gather, D=64 floats (16 float4), 2 edges per iteration
__global__ void k_agg64(const float* __restrict__ S, float* __restrict__ Dst, int n) {
    int w = (blockIdx.x * blockDim.x + threadIdx.x) >> 5;
    int lane = threadIdx.x & 31;
    if (w >= n) return;
    int cnt = g_indeg[w];
    const int* cs = g_csr_src + (size_t)w * SLOT;
    const float* cw = g_csr_w + (size_t)w * SLOT;
    int hh = lane >> 4, l = lane & 15;
    const float4* S4 = reinterpret_cast<const float4*>(S);
    float4 acc = make_float4(0.f, 0.f, 0.f, 0.f);
#pragma unroll 4
    for (int e = 0; e < cnt; e += 2) {
        int ee = e + hh;
        bool ok = ee < cnt;
        int s = ok ? cs[ee] : 0;
        float wgt = ok ? cw[ee] : 0.0f;
        float4 v = S4[(size_t)s * 16 + l];
        acc.x += wgt * v.x; acc.y += wgt * v.y; acc.z += wgt * v.z; acc.w += wgt * v.w;
    }
    acc.x += __shfl_xor_sync(0xffffffff, acc.x, 16);
    acc.y += __shfl_xor_sync(0xffffffff, acc.y, 16);
    acc.z += __shfl_xor_sync(0xffffffff, acc.z, 16);
    acc.w += __shfl_xor_sync(0xffffffff, acc.w, 16);
    if (lane < 16) reinterpret_cast<float4*>(Dst)[(size_t)w * 16 + lane] = acc;
}

// warp-per-dst gather, D=32 floats (8 float4), 4 edges per iteration
template <bool FINAL>
__global__ void k_agg32(const float* __restrict__ S, const float* __restrict__ bias,
                        float* __restrict__ Dst, int n) {
    int w = (blockIdx.x * blockDim.x + threadIdx.x) >> 5;
    int lane = threadIdx.x & 31;
    if (w >= n) return;
    int cnt = g_indeg[w];
    const int* cs = g_csr_src + (size_t)w * SLOT;
    const float* cw = g_csr_w + (size_t)w * SLOT;
    int q = lane >> 3, l = lane & 7;
    const float4* S4 = reinterpret_cast<const float4*>(S);
    float4 acc = make_float4(0.f, 0.f, 0.f, 0.f);
#pragma unroll 4
    for (int e = 0; e < cnt; e += 4) {
        int ee = e + q;
        bool ok = ee < cnt;
        int s = ok ? cs[ee] : 0;
        float wgt = ok ? cw[ee] : 0.0f;
        float4 v = S4[(size_t)s * 8 + l];
        acc.x += wgt * v.x; acc.y += wgt * v.y; acc.z += wgt * v.z; acc.w += wgt * v.w;
    }
#pragma unroll
    for (int m = 8; m <= 16; m <<= 1) {
        acc.x += __shfl_xor_sync(0xffffffff, acc.x, m);
        acc.y += __shfl_xor_sync(0xffffffff, acc.y, m);
        acc.z += __shfl_xor_sync(0xffffffff, acc.z, m);
        acc.w += __shfl_xor_sync(0xffffffff, acc.w, m);
    }
    if (lane < 8) {
        if (FINAL) {
            float4 b = reinterpret_cast<const float4*>(bias)[lane];
            acc.x += b.x; acc.y += b.y; acc.z += b.z; acc.w += b.w;
        }
        reinterpret_cast<float4*>(Dst)[(size_t)w * 8 + lane] = acc;
    }
}

// ---------------- launch ----------------
extern "C" void kernel_launch(void* const* d_in, const int* in_sizes, int n_in,
                              void* d_out, int out_size) {
    const float* feat = (const float*)d_in[0];
    const int* esrc = (const int*)d_in[1];
    const int* edst = (const int*)d_in[2];
    const float* ew = (const float*)d_in[3];
    const float* Wih = (const float*)d_in[4];
    const float* Whh = (const float*)d_in[5];
    const float* bih = (const float*)d_in[6];
    const float* bhh = (const float*)d_in[7];
    const float* W0 = (const float*)d_in[8];
    const float* b0 = (const float*)d_in[9];
    const float* W1 = (const float*)d_in[10];
    const float* b1 = (const float*)d_in[11];
    const float* W2 = (const float*)d_in[12];
    const float* b2 = (const float*)d_in[13];
    float* out = (float*)d_out;

    int n = in_sizes[0] / 8;
    int E = in_sizes[1];

    void *p_h0, *p_agg, *p_out0, *p_out1, *p_m2;
    cudaGetSymbolAddress(&p_h0, g_h0);
    cudaGetSymbolAddress(&p_agg, g_agg);
    cudaGetSymbolAddress(&p_out0, g_out0);
    cudaGetSymbolAddress(&p_out1, g_out1);
    cudaGetSymbolAddress(&p_m2, g_m2);

    const int TB = 256;
    k_zero<<<(n + TB - 1) / TB, TB>>>(n);
    k_norm_u<<<(n + 255) / 256, 256>>>(feat, Wih, bih, bhh, n);
    k_edge<<<(E + TB - 1) / TB, TB>>>(esrc, edst, ew, E);
    k_fixw<<<(n * 32 + TB - 1) / TB, TB>>>(n);
    k_lstm<<<(n + 127) / 128, 128>>>(Whh, bih, bhh, n);

    const int AT = 256;
    int aggBlocks = (n + (AT / 32) - 1) / (AT / 32);

    // layer 0: aggregate h0 (stride 32, first 24 cols live), then GEMM 24->64
    k_agg32<false><<<aggBlocks, AT>>>((const float*)p_h0, nullptr, (float*)p_agg, n);
    k_gemm<24, 64, 32, true><<<(n + 127) / 128, 128>>>((const float*)p_agg, W0, b0, (float*)p_out0, n);

    // layer 1: aggregate out0 (64), then GEMM 64->64
    k_agg64<<<aggBlocks, AT>>>((const float*)p_out0, (float*)p_agg, n);
    k_gemm<64, 64, 64, true><<<(n + 127) / 128, 128>>>((const float*)p_agg, W1, b1, (float*)p_out1, n);

    // layer 2: GEMM 64->32, then aggregate (32) + bias -> output
    k_gemm<64, 32, 64, false><<<(n + 127) / 128, 128>>>((const float*)p_out1, W2, nullptr, (float*)p_m2, n);
    k_agg32<true><<<aggBlocks, AT>>>((const float*)p_m2, b2, out, n);
}